// round 16
// baseline (speedup 1.0000x reference)
#include <cuda_runtime.h>
#include <math.h>

// Problem constants
#define B_   64
#define S_   4096
#define ENC_ 512
#define DEC_ 512

#define NCTA   740                 // 148 SMs * 5 CTAs  (one even wave at 5/SM)
#define TROWS  355                 // rows per CTA (740*355 = 262700 >= 262144)
#define GROWS  (B_ * S_)           // 262144 global rows
#define MAXSLOT 16                 // max partial-slots per batch (need <= 13)

// ---- scratch (no allocations allowed; __device__ globals) ----
__device__ float g_sub[B_ * ENC_];             // dec @ W^T             (128 KB)
__device__ float g_logits[B_ * S_];            // raw attention logits  (1 MB)
__device__ float g_pm[B_ * MAXSLOT];           // per-slot max
__device__ float g_pl[B_ * MAXSLOT];           // per-slot denom
__device__ float g_pacc[B_ * MAXSLOT * ENC_];  // per-slot weighted sums (2 MB)
__device__ unsigned g_ns[B_];                  // slots used per batch
__device__ unsigned g_cnt[B_];                 // rows completed per batch

// ============================================================
// Kernel 1: sub[b,e] = sum_d dec[b,d] * W[e,d]   (R2 version, best measured)
// grid = (8, 64), block = 256. Also resets counters (runs before pass1).
// ============================================================
__global__ __launch_bounds__(256) void sub_kernel(const float* __restrict__ dec,
                                                  const float* __restrict__ W) {
    const int et   = blockIdx.x;
    const int b    = blockIdx.y;
    const int tid  = threadIdx.x;
    const int w    = tid >> 5;
    const int lane = tid & 31;

    if (et == 0 && tid == 0) { g_cnt[b] = 0; g_ns[b] = 0; }

    __shared__ float dsm[DEC_];
    for (int i = tid; i < DEC_; i += 256) dsm[i] = dec[b * DEC_ + i];
    __syncthreads();

    const float4* d4 = (const float4*)dsm;
    float4 dv[4];
#pragma unroll
    for (int j = 0; j < 4; j++) dv[j] = d4[lane + 32 * j];

    const int e0 = et * 64 + w * 8;
#pragma unroll
    for (int i = 0; i < 8; i++) {
        const int e = e0 + i;
        const float4* Wr = (const float4*)(W + (size_t)e * DEC_);
        float s = 0.f;
#pragma unroll
        for (int j = 0; j < 4; j++) {
            float4 wv = Wr[lane + 32 * j];
            s += wv.x * dv[j].x + wv.y * dv[j].y + wv.z * dv[j].z + wv.w * dv[j].w;
        }
#pragma unroll
        for (int o = 16; o > 0; o >>= 1) s += __shfl_xor_sync(0xffffffffu, s, o);
        if (lane == 0) g_sub[b * ENC_ + e] = s;
    }
}

// ============================================================
// Kernel 2: streaming pass, 5 CTAs/SM (Little's-law fix) + fused finalize.
// grid = 740 flat CTAs, block = 256 (8 warps), __launch_bounds__(256,5).
// Lean loop: no subr registers (sub read from smem; extra warps hide LDS),
// branch-optimized online-softmax update (bit-exact), contiguous rows.
// ============================================================
__global__ __launch_bounds__(256, 5) void attn_pass1(const float* __restrict__ enc,
                                                     float* __restrict__ out) {
    const int tid  = threadIdx.x;
    const int w    = tid >> 5;
    const int lane = tid & 31;

    const int row0 = blockIdx.x * TROWS;
    const int row1 = min(row0 + TROWS, GROWS);

    __shared__ float subsm[ENC_];
    __shared__ float accsm[8][ENC_];     // 16 KB
    __shared__ float msm[8], lsm[8];
    __shared__ int   slot_sh;
    __shared__ bool  is_last;

    const float4* sub4 = (const float4*)subsm;

    int row = row0;
    while (row < row1) {
        const int b      = row >> 12;                 // row / 4096
        const int segend = min(row1, (b + 1) << 12);
        const int nrows  = segend - row;

        __syncthreads();                              // protect subsm/accsm reuse
        for (int i = tid; i < ENC_; i += 256) subsm[i] = g_sub[b * ENC_ + i];
        __syncthreads();

        float m = -1e30f;
        float l = 0.f;
        float4 acc[4];
#pragma unroll
        for (int j = 0; j < 4; j++) acc[j] = make_float4(0.f, 0.f, 0.f, 0.f);

        const float* encb = enc + (size_t)b * S_ * ENC_;

        for (int s = row + w; s < segend; s += 8) {
            const int sl = s - (b << 12);             // row within batch
            const float4* er = (const float4*)(encb + (size_t)sl * ENC_);

            float4 ev[4];
#pragma unroll
            for (int j = 0; j < 4; j++) ev[j] = __ldcs(&er[lane + 32 * j]);

            float dot = 0.f;
#pragma unroll
            for (int j = 0; j < 4; j++) {
                const float4 sv = sub4[lane + 32 * j];   // LDS (hidden by warps)
                dot += ev[j].x * sv.x + ev[j].y * sv.y + ev[j].z * sv.z + ev[j].w * sv.w;
            }
#pragma unroll
            for (int o = 16; o > 0; o >>= 1) dot += __shfl_xor_sync(0xffffffffu, dot, o);

            if (lane == 0) g_logits[b * S_ + sl] = dot;

            // online softmax — warp-uniform branch (bit-exact, shorter chain)
            if (dot <= m) {
                const float p = __expf(dot - m);
                l += p;
#pragma unroll
                for (int j = 0; j < 4; j++) {
                    acc[j].x += p * ev[j].x;
                    acc[j].y += p * ev[j].y;
                    acc[j].z += p * ev[j].z;
                    acc[j].w += p * ev[j].w;
                }
            } else {
                const float scale = __expf(m - dot);
                l = l * scale + 1.0f;
#pragma unroll
                for (int j = 0; j < 4; j++) {
                    acc[j].x = acc[j].x * scale + ev[j].x;
                    acc[j].y = acc[j].y * scale + ev[j].y;
                    acc[j].z = acc[j].z * scale + ev[j].z;
                    acc[j].w = acc[j].w * scale + ev[j].w;
                }
                m = dot;
            }
        }

        // spill warp state to smem
        float4* arow = (float4*)accsm[w];
#pragma unroll
        for (int j = 0; j < 4; j++) arow[lane + 32 * j] = acc[j];
        if (lane == 0) { msm[w] = m; lsm[w] = l; }
        __syncthreads();

        // block merge
        float M = -1e30f;
#pragma unroll
        for (int ww = 0; ww < 8; ww++) M = fmaxf(M, msm[ww]);
        float L = 0.f;
        float wts[8];
#pragma unroll
        for (int ww = 0; ww < 8; ww++) {
            wts[ww] = __expf(msm[ww] - M);
            L += lsm[ww] * wts[ww];
        }

        // flush to a dynamically-allocated slot for batch b
        if (tid == 0) slot_sh = (int)atomicAdd(&g_ns[b], 1u);
        __syncthreads();
        const int sid = b * MAXSLOT + slot_sh;
        if (tid == 0) { g_pm[sid] = M; g_pl[sid] = L; }
        for (int e = tid; e < ENC_; e += 256) {
            float a = 0.f;
#pragma unroll
            for (int ww = 0; ww < 8; ww++) a += accsm[ww][e] * wts[ww];
            g_pacc[(size_t)sid * ENC_ + e] = a;
        }

        // ticket: rows complete for batch b
        __threadfence();
        __syncthreads();
        if (tid == 0) {
            unsigned done = atomicAdd(&g_cnt[b], (unsigned)nrows) + (unsigned)nrows;
            is_last = (done == (unsigned)S_);
        }
        __syncthreads();

        if (is_last) {
            __threadfence();
            const int ns = (int)g_ns[b];
            float Mg = -1e30f;
            for (int cc = 0; cc < ns; cc++) Mg = fmaxf(Mg, g_pm[b * MAXSLOT + cc]);
            float Lg = 0.f;
            for (int cc = 0; cc < ns; cc++)
                Lg += g_pl[b * MAXSLOT + cc] * __expf(g_pm[b * MAXSLOT + cc] - Mg);
            const float invL = 1.f / Lg;

            const float* lg = g_logits + b * S_;
            float* attn_out = out + (size_t)b * S_;
            for (int s = tid; s < S_; s += 256)
                attn_out[s] = __expf(lg[s] - Mg) * invL;

            float* sum_out = out + (size_t)B_ * S_ + (size_t)b * ENC_;
            for (int e = tid; e < ENC_; e += 256) {
                float a = 0.f;
                for (int cc = 0; cc < ns; cc++)
                    a += g_pacc[(size_t)(b * MAXSLOT + cc) * ENC_ + e]
                         * __expf(g_pm[b * MAXSLOT + cc] - Mg);
                sum_out[e] = a * invL;
            }
        }

        row = segend;
    }
}

// ============================================================
extern "C" void kernel_launch(void* const* d_in, const int* in_sizes, int n_in,
                              void* d_out, int out_size) {
    const float* dec = (const float*)d_in[0];  // [64,1,512]
    const float* enc = (const float*)d_in[1];  // [64,4096,512]
    const float* W   = (const float*)d_in[2];  // [512,512]
    float* out = (float*)d_out;

    sub_kernel<<<dim3(ENC_ / 64, B_), 256>>>(dec, W);
    attn_pass1<<<NCTA, 256>>>(enc, out);
}